// round 1
// baseline (speedup 1.0000x reference)
#include <cuda_runtime.h>

// ContrastiveLoss: only ~100 pairs (pure function of subject_ids) matter.
// Pipeline: order-preserving chunked counting sort of subject ids (first 51
// indices per subject suffice for the exact enumeration), serial pair build
// replicating the reference loop order, then warp-per-pair normalized dot +
// stable BCE.

#define NSUBJ 1024
#define NCHUNK 256
#define MAXP 50
#define CAP 51   // max occurrence indices per subject ever touched by the algorithm

__device__ int g_counts[NSUBJ * NCHUNK];   // [subject][chunk] counts -> offsets
__device__ int g_cnt[NSUBJ];               // total count per subject
__device__ int g_idx[NSUBJ * CAP];         // first CAP indices per subject (ascending)
__device__ int g_ii[2 * MAXP];             // pos pairs at [0..npos), neg at [MAXP..MAXP+nneg)
__device__ int g_jj[2 * MAXP];
__device__ int g_npn[2];                   // {npos, nneg}

// subject_ids may arrive as int64 or (jax default-x64-off) int32. Detect:
// 16 consecutive int64 reads all in [0, NSUBJ) <=> genuinely int64.
__device__ __forceinline__ bool detect64(const void* p) {
    const long long* q = (const long long*)p;
    bool ok = true;
#pragma unroll
    for (int k = 0; k < 16; k++) {
        long long v = q[k];
        ok = ok && (v >= 0 && v < (long long)NSUBJ);
    }
    return ok;
}

__device__ __forceinline__ int sid_at(const void* p, int i, bool is64) {
    return is64 ? (int)((const long long*)p)[i] : ((const int*)p)[i];
}

// ---- Phase 1: per-chunk histogram (thread c owns chunk c; column-exclusive) ----
__global__ void k_count(const void* sids, int B) {
    int c = threadIdx.x;                 // 0..NCHUNK-1
    bool is64 = detect64(sids);
    int chunk = (B + NCHUNK - 1) / NCHUNK;
#pragma unroll 4
    for (int s = 0; s < NSUBJ; s++) g_counts[s * NCHUNK + c] = 0;
    int base = c * chunk;
    for (int k = 0; k < chunk; k++) {
        int i = base + k;
        if (i >= B) break;
        int s = sid_at(sids, i, is64);
        g_counts[s * NCHUNK + c]++;      // exclusive owner of column c: no atomics
    }
}

// ---- Phase 2: per-subject exclusive prefix over chunks ----
__global__ void k_prefix() {
    int s = threadIdx.x;                 // 0..NSUBJ-1
    int run = 0;
    for (int c = 0; c < NCHUNK; c++) {
        int v = g_counts[s * NCHUNK + c];
        g_counts[s * NCHUNK + c] = run;
        run += v;
    }
    g_cnt[s] = run;
}

// ---- Phase 3: order-preserving scatter of first CAP indices per subject ----
__global__ void k_scatter(const void* sids, int B) {
    int c = threadIdx.x;
    bool is64 = detect64(sids);
    int chunk = (B + NCHUNK - 1) / NCHUNK;
    int base = c * chunk;
    for (int k = 0; k < chunk; k++) {
        int i = base + k;
        if (i >= B) break;
        int s = sid_at(sids, i, is64);
        int off = g_counts[s * NCHUNK + c];
        g_counts[s * NCHUNK + c] = off + 1;
        if (off < CAP) g_idx[s * CAP + off] = i;
    }
}

// ---- Phase 4: exact replica of the reference pair-enumeration loop ----
__global__ void k_pairs() {
    __shared__ int scnt[NSUBJ];
    for (int s = threadIdx.x; s < NSUBJ; s += blockDim.x) scnt[s] = g_cnt[s];
    __syncthreads();
    if (threadIdx.x != 0) return;

    int npos = 0, nneg = 0;
    for (int s = 0; s < NSUBJ; s++) {
        int cs = scnt[s];
        if (cs == 0) continue;           // s ranges over uniq (sorted ascending)
        int til = cs < CAP ? cs : CAP;
        if (cs >= 2 && npos < MAXP) {
            for (int a = 0; a < til && npos < MAXP; a++)
                for (int b = a + 1; b < til && npos < MAXP; b++) {
                    g_ii[npos] = g_idx[s * CAP + a];
                    g_jj[npos] = g_idx[s * CAP + b];
                    npos++;
                }
        }
        for (int o = 0; o < NSUBJ; o++) {
            int co = scnt[o];
            if (co == 0) continue;       // uniq membership
            if (o == s) continue;        // python: continue before break check
            if (nneg >= MAXP) break;
            int tjl = co < CAP ? co : CAP;
            for (int a = 0; a < til && nneg < MAXP; a++)
                for (int b = 0; b < tjl && nneg < MAXP; b++) {
                    g_ii[MAXP + nneg] = g_idx[s * CAP + a];
                    g_jj[MAXP + nneg] = g_idx[o * CAP + b];
                    nneg++;
                }
        }
        if (npos >= MAXP && nneg >= MAXP) break;
    }
    g_npn[0] = npos;
    g_npn[1] = nneg;
}

// ---- Phase 5: warp-per-pair normalized dot + stable BCE, block reduce ----
__global__ void k_loss(const float* __restrict__ x, float* __restrict__ out, int D) {
    int tid = threadIdx.x, lane = tid & 31, wid = tid >> 5;
    int npos = g_npn[0], nneg = g_npn[1], n = npos + nneg;

    float acc = 0.0f;
    int nvec = D / 4;  // D = 384 -> 96 float4, 3 per lane
    for (int p = wid; p < n; p += 32) {
        int slot = (p < npos) ? p : (MAXP + (p - npos));
        int i = g_ii[slot], j = g_jj[slot];
        const float4* xi = (const float4*)(x + (long long)i * D);
        const float4* xj = (const float4*)(x + (long long)j * D);
        float sxx = 0.f, syy = 0.f, sxy = 0.f;
        for (int q = lane; q < nvec; q += 32) {
            float4 a = xi[q];
            float4 b = xj[q];
            sxx += a.x * a.x + a.y * a.y + a.z * a.z + a.w * a.w;
            syy += b.x * b.x + b.y * b.y + b.z * b.z + b.w * b.w;
            sxy += a.x * b.x + a.y * b.y + a.z * b.z + a.w * b.w;
        }
#pragma unroll
        for (int off = 16; off; off >>= 1) {
            sxx += __shfl_xor_sync(0xFFFFFFFFu, sxx, off);
            syy += __shfl_xor_sync(0xFFFFFFFFu, syy, off);
            sxy += __shfl_xor_sync(0xFFFFFFFFu, sxy, off);
        }
        float ni = fmaxf(sqrtf(sxx), 1e-12f);
        float nj = fmaxf(sqrtf(syy), 1e-12f);
        float s = (sxy / (ni * nj)) * 2.0f;   // / TEMPERATURE (0.5)
        float xs = (p < npos) ? -s : s;       // -label*logsig(s)-(1-l)*logsig(-s)
        acc += fmaxf(xs, 0.f) + log1pf(expf(-fabsf(xs)));  // softplus(xs)
    }

    __shared__ float part[32];
    if (lane == 0) part[wid] = acc;   // every warp writes (0 if no pairs)
    __syncthreads();
    if (wid == 0) {
        float v = part[lane];
#pragma unroll
        for (int off = 16; off; off >>= 1) v += __shfl_xor_sync(0xFFFFFFFFu, v, off);
        if (lane == 0) out[0] = v / (float)n;
    }
}

extern "C" void kernel_launch(void* const* d_in, const int* in_sizes, int n_in,
                              void* d_out, int out_size) {
    const float* x = (const float*)d_in[0];   // identity_tokens [B, D] fp32
    const void* sids = d_in[1];               // subject_ids [B] int32 or int64
    int B = in_sizes[1];
    int D = in_sizes[0] / B;

    k_count<<<1, NCHUNK>>>(sids, B);
    k_prefix<<<1, NSUBJ>>>();
    k_scatter<<<1, NCHUNK>>>(sids, B);
    k_pairs<<<1, 256>>>();
    k_loss<<<1, 1024>>>(x, (float*)d_out, D);
}

// round 3
// speedup vs baseline: 4.2131x; 4.2131x over previous
#include <cuda_runtime.h>

// Fully fused ContrastiveLoss: one block, one launch.
// Phase 1: per-(subject,warp) u16 counts in smem via __match_any_sync.
// Phase 2: per-subject exclusive prefix over warps (thread s scans 32 vals).
// Phase 3: replay pass, order-preserving scatter of first CAP indices (u16) to smem.
// Phase 4: thread 0 replicates the exact reference pair-enumeration loop (all smem).
// Phase 5: warp-per-pair normalized dot + stable BCE, block reduce, store loss.
// R2 bug fixed: after the per-pair shfl reduction every lane holds the full
// per-pair loss, so the warp partial is lane 0's acc — do NOT shfl-reduce acc.

#define NSUBJ 1024
#define NWARP 32
#define MAXP 50
#define CAP 51   // max occurrence indices per subject the enumeration can touch

#define WCNT_B (NSUBJ * NWARP * 2)        // 65536
#define SIDX_B (NSUBJ * CAP * 2)          // 104448
#define SCNT_B (NSUBJ * 4)                // 4096
#define SMEM_TOTAL (WCNT_B + SIDX_B + SCNT_B + 2 * MAXP * 2 * 4 + 8 + 128)

// subject_ids may be int64 or (jax x64-off) int32. 16 consecutive int64 reads
// all in [0, NSUBJ) <=> genuinely int64.
__device__ __forceinline__ bool detect64(const void* p) {
    const long long* q = (const long long*)p;
    bool ok = true;
#pragma unroll
    for (int k = 0; k < 16; k++) {
        long long v = q[k];
        ok = ok && (v >= 0 && v < (long long)NSUBJ);
    }
    return ok;
}

__device__ __forceinline__ int sid_at(const void* p, int i, bool is64) {
    return is64 ? (int)((const long long*)p)[i] : ((const int*)p)[i];
}

__global__ void __launch_bounds__(1024, 1)
fused_contrastive(const void* __restrict__ sids, const float* __restrict__ x,
                  float* __restrict__ out, int B, int D) {
    extern __shared__ unsigned char sm[];
    unsigned short* wcnt = (unsigned short*)sm;                       // [s*32+w]
    unsigned short* sidx = (unsigned short*)(sm + WCNT_B);            // [s*CAP+slot]
    int* scnt = (int*)(sm + WCNT_B + SIDX_B);                         // [s]
    int* ii   = scnt + NSUBJ;                                         // pos [0..MAXP), neg [MAXP..2*MAXP)
    int* jj   = ii + 2 * MAXP;
    int* npn  = jj + 2 * MAXP;                                        // {npos, nneg}
    float* part = (float*)(npn + 2);                                  // [32]

    const int tid = threadIdx.x, lane = tid & 31, w = tid >> 5;
    const bool is64 = detect64(sids);

    // zero wcnt (as u32 words)
    {
        unsigned int* z = (unsigned int*)wcnt;
        for (int k = tid; k < WCNT_B / 4; k += 1024) z[k] = 0u;
    }
    __syncthreads();

    // warp w owns contiguous element range [w*iters*32, (w+1)*iters*32)
    const int iters = (B + NWARP * 32 - 1) / (NWARP * 32);
    const int base = w * iters * 32;

    // ---- Phase 1: counts per (subject, warp) ----
    for (int k = 0; k < iters; k++) {
        int i = base + k * 32 + lane;
        bool valid = i < B;
        int s = valid ? sid_at(sids, i, is64) : 0;
        int key = valid ? s : (NSUBJ + lane);          // invalid lanes: singleton keys
        unsigned mask = __match_any_sync(0xFFFFFFFFu, key);
        if (valid && lane == (__ffs(mask) - 1))
            wcnt[s * NWARP + w] = (unsigned short)(wcnt[s * NWARP + w] + __popc(mask));
    }
    __syncthreads();

    // ---- Phase 2: per-subject exclusive prefix over warps ----
    {
        int s = tid;  // blockDim == 1024 == NSUBJ
        int run = 0;
#pragma unroll
        for (int c = 0; c < NWARP; c++) {
            int v = wcnt[s * NWARP + c];
            wcnt[s * NWARP + c] = (unsigned short)run;
            run += v;
        }
        scnt[s] = run;
    }
    __syncthreads();

    // ---- Phase 3: order-preserving scatter of first CAP indices (u16) ----
    for (int k = 0; k < iters; k++) {
        int i = base + k * 32 + lane;
        bool valid = i < B;
        int s = valid ? sid_at(sids, i, is64) : 0;
        int key = valid ? s : (NSUBJ + lane);
        unsigned mask = __match_any_sync(0xFFFFFFFFu, key);
        if (valid) {
            int rank = __popc(mask & ((1u << lane) - 1u));
            int cur = wcnt[s * NWARP + w];               // all lanes read before leader's store
            int slot = cur + rank;
            if (lane == (__ffs(mask) - 1))
                wcnt[s * NWARP + w] = (unsigned short)(cur + __popc(mask));
            if (slot < CAP) sidx[s * CAP + slot] = (unsigned short)i;
        }
    }
    __syncthreads();

    // ---- Phase 4: exact replica of reference pair enumeration (thread 0, all smem) ----
    if (tid == 0) {
        int npos = 0, nneg = 0;
        for (int s = 0; s < NSUBJ; s++) {
            int cs = scnt[s];
            if (cs == 0) continue;                       // uniq membership (sorted ascending)
            int til = cs < CAP ? cs : CAP;
            if (cs >= 2 && npos < MAXP) {
                for (int a = 0; a < til && npos < MAXP; a++)
                    for (int b = a + 1; b < til && npos < MAXP; b++) {
                        ii[npos] = sidx[s * CAP + a];
                        jj[npos] = sidx[s * CAP + b];
                        npos++;
                    }
            }
            for (int o = 0; o < NSUBJ; o++) {
                int co = scnt[o];
                if (co == 0) continue;
                if (o == s) continue;                    // python: continue precedes break check
                if (nneg >= MAXP) break;
                int tjl = co < CAP ? co : CAP;
                for (int a = 0; a < til && nneg < MAXP; a++)
                    for (int b = 0; b < tjl && nneg < MAXP; b++) {
                        ii[MAXP + nneg] = sidx[s * CAP + a];
                        jj[MAXP + nneg] = sidx[o * CAP + b];
                        nneg++;
                    }
            }
            if (npos >= MAXP && nneg >= MAXP) break;
        }
        npn[0] = npos;
        npn[1] = nneg;
    }
    __syncthreads();

    // ---- Phase 5: warp-per-pair normalized dot + stable BCE ----
    const int npos = npn[0], nneg = npn[1], n = npos + nneg;
    float acc = 0.0f;
    const int nvec = D / 4;                              // D=384 -> 96 float4
    for (int p = w; p < n; p += NWARP) {
        int slot = (p < npos) ? p : (MAXP + (p - npos));
        int i = ii[slot], j = jj[slot];
        const float4* xi = (const float4*)(x + (long long)i * D);
        const float4* xj = (const float4*)(x + (long long)j * D);
        float sxx = 0.f, syy = 0.f, sxy = 0.f;
        for (int q = lane; q < nvec; q += 32) {
            float4 a = xi[q];
            float4 b = xj[q];
            sxx += a.x * a.x + a.y * a.y + a.z * a.z + a.w * a.w;
            syy += b.x * b.x + b.y * b.y + b.z * b.z + b.w * b.w;
            sxy += a.x * b.x + a.y * b.y + a.z * b.z + a.w * b.w;
        }
#pragma unroll
        for (int off = 16; off; off >>= 1) {
            sxx += __shfl_xor_sync(0xFFFFFFFFu, sxx, off);
            syy += __shfl_xor_sync(0xFFFFFFFFu, syy, off);
            sxy += __shfl_xor_sync(0xFFFFFFFFu, sxy, off);
        }
        // every lane now holds the full sums; acc is replicated across lanes
        float ni = fmaxf(sqrtf(sxx), 1e-12f);
        float nj = fmaxf(sqrtf(syy), 1e-12f);
        float sc = (sxy / (ni * nj)) * 2.0f;             // / TEMPERATURE (0.5)
        float xs = (p < npos) ? -sc : sc;
        acc += fmaxf(xs, 0.f) + log1pf(expf(-fabsf(xs)));  // softplus(xs)
    }

    // acc is identical on all lanes of the warp -> lane 0's copy IS the warp partial
    if (lane == 0) part[w] = acc;
    __syncthreads();
    if (w == 0) {
        float v = part[lane];
#pragma unroll
        for (int off = 16; off; off >>= 1) v += __shfl_xor_sync(0xFFFFFFFFu, v, off);
        if (lane == 0) out[0] = v / (float)n;
    }
}

extern "C" void kernel_launch(void* const* d_in, const int* in_sizes, int n_in,
                              void* d_out, int out_size) {
    const float* x = (const float*)d_in[0];   // identity_tokens [B, D] fp32
    const void* sids = d_in[1];               // subject_ids [B]
    int B = in_sizes[1];
    int D = in_sizes[0] / B;

    cudaFuncSetAttribute(fused_contrastive,
                         cudaFuncAttributeMaxDynamicSharedMemorySize, SMEM_TOTAL);

    fused_contrastive<<<1, 1024, SMEM_TOTAL>>>(sids, x, (float*)d_out, B, D);
}